// round 2
// baseline (speedup 1.0000x reference)
#include <cuda_runtime.h>
#include <cuda_fp16.h>

#define D_DIM 512
#define C_DIM 1024
#define M_TILE 64
#define QS_STRIDE 520   // halves: 64-row q tile, padded for conflict-free frag loads
#define WS_STRIDE 1032  // halves: 64x1024 w tile
#define KS_STRIDE 72    // halves: 128x64 staging chunk

// Device-global scratch (no allocations allowed in kernel_launch)
__device__ __half g_Kh[C_DIM * D_DIM];   // normalized keys, (c, d) row-major, fp16
__device__ __half g_Vt[C_DIM * C_DIM];   // val transposed:  g_Vt[n*C + k] = val[k*C + n], fp16

// sharp(x) = sigmoid(10x - 5) + sigmoid(-10x - 5)
__device__ __forceinline__ float sharp_fn(float x) {
    float t = 10.f * x;
    return 1.f / (1.f + __expf(5.f - t)) + 1.f / (1.f + __expf(5.f + t));
}

__device__ __forceinline__ void mma16816(float c[4], const unsigned a[4], const unsigned b[2]) {
    asm volatile(
        "mma.sync.aligned.m16n8k16.row.col.f32.f16.f16.f32 "
        "{%0,%1,%2,%3}, {%4,%5,%6,%7}, {%8,%9}, {%0,%1,%2,%3};\n"
        : "+f"(c[0]), "+f"(c[1]), "+f"(c[2]), "+f"(c[3])
        : "r"(a[0]), "r"(a[1]), "r"(a[2]), "r"(a[3]), "r"(b[0]), "r"(b[1]));
}

// ---------------------------------------------------------------------------
// Prep 1: l2-normalize each key row, store fp16
// ---------------------------------------------------------------------------
__global__ void normalize_key_kernel(const float* __restrict__ key) {
    const int r = blockIdx.x;
    const int tid = threadIdx.x;  // 128 threads
    const float* kr = key + (size_t)r * D_DIM;
    float v[4];
    float ss = 0.f;
#pragma unroll
    for (int i = 0; i < 4; ++i) { v[i] = kr[tid + i * 128]; ss += v[i] * v[i]; }
    __shared__ float ws[4];
    __shared__ float sinv;
#pragma unroll
    for (int o = 16; o > 0; o >>= 1) ss += __shfl_down_sync(0xffffffffu, ss, o);
    if ((tid & 31) == 0) ws[tid >> 5] = ss;
    __syncthreads();
    if (tid == 0) sinv = rsqrtf(ws[0] + ws[1] + ws[2] + ws[3] + 1e-12f);
    __syncthreads();
    const float iv = sinv;
#pragma unroll
    for (int i = 0; i < 4; ++i)
        g_Kh[(size_t)r * D_DIM + tid + i * 128] = __float2half(v[i] * iv);
}

// ---------------------------------------------------------------------------
// Prep 2: transpose val -> g_Vt (fp16). g_Vt[n][k] = val[k][n]
// ---------------------------------------------------------------------------
__global__ void transpose_val_kernel(const float* __restrict__ val) {
    __shared__ float tile[32][33];
    const int ko = blockIdx.x * 32;
    const int no = blockIdx.y * 32;
    const int tx = threadIdx.x, ty = threadIdx.y;  // (32, 8)
#pragma unroll
    for (int j = 0; j < 32; j += 8)
        tile[ty + j][tx] = val[(size_t)(ko + ty + j) * C_DIM + no + tx];
    __syncthreads();
#pragma unroll
    for (int j = 0; j < 32; j += 8)
        g_Vt[(size_t)(no + ty + j) * C_DIM + ko + tx] = __float2half(tile[tx][ty + j]);
}

// ---------------------------------------------------------------------------
// Fused main kernel: per 64-row tile of query:
//   normalize q -> GEMM1 (sim) -> sharpen (w tile in smem) -> rowsum ->
//   GEMM2 (w @ val) -> scale by 1/rowsum -> out
// ---------------------------------------------------------------------------
__global__ __launch_bounds__(256, 1)
void fused_kv_kernel(const float* __restrict__ query, float* __restrict__ out) {
    extern __shared__ __half sh[];
    __half* Qs = sh;                               // 64 x QS_STRIDE
    __half* Ws = Qs + M_TILE * QS_STRIDE;          // 64 x WS_STRIDE
    __half* Ks = Ws + M_TILE * WS_STRIDE;          // 128 x KS_STRIDE (K or V staging)
    float*  red = (float*)(Ks + 128 * KS_STRIDE);  // 256 floats
    float*  inv = red + 256;                       // 64 floats

    const int tid  = threadIdx.x;
    const int lane = tid & 31;
    const int wid  = tid >> 5;
    const int g    = lane >> 2;   // mma group id (row within tile)
    const int tig  = lane & 3;    // thread in group
    const int wm   = wid >> 2;    // warp m: 0..1
    const int wn   = wid & 3;     // warp n: 0..3
    const int row0 = blockIdx.x * M_TILE;

    // ---- Step 0: load + l2-normalize Q tile into smem fp16 ----
    {
        const int r = tid >> 2;       // 0..63
        const int p = tid & 3;        // quarter of the row
        const float* qrow = query + (size_t)(row0 + r) * D_DIM + p * 128;
        __half* qd = Qs + r * QS_STRIDE + p * 128;
        float ss = 0.f;
#pragma unroll 8
        for (int i = 0; i < 128; i += 4) {
            float4 v = *(const float4*)(qrow + i);
            ss += v.x * v.x + v.y * v.y + v.z * v.z + v.w * v.w;
            *(__half2*)(qd + i)     = __floats2half2_rn(v.x, v.y);
            *(__half2*)(qd + i + 2) = __floats2half2_rn(v.z, v.w);
        }
        red[tid] = ss;
        __syncthreads();
        if (tid < M_TILE)
            inv[tid] = rsqrtf(red[tid * 4] + red[tid * 4 + 1] +
                              red[tid * 4 + 2] + red[tid * 4 + 3] + 1e-12f);
        __syncthreads();
        const float qin = inv[r];
#pragma unroll 8
        for (int i = 0; i < 128; i += 2) {
            float2 f = __half22float2(*(__half2*)(qd + i));
            *(__half2*)(qd + i) = __floats2half2_rn(f.x * qin, f.y * qin);
        }
    }
    __syncthreads();

    const int srow = tid >> 1;        // staging row 0..127
    const int scol = (tid & 1) * 32;  // staging col base (halves)

    // ---- Step 1: GEMM1 (sim = Qn @ Kn^T) + sharpening into Ws ----
#pragma unroll 1
    for (int nc = 0; nc < 8; ++nc) {
        const int n0 = nc * 128;
        float acc[2][4][4];
#pragma unroll
        for (int mi = 0; mi < 2; ++mi)
#pragma unroll
            for (int ni = 0; ni < 4; ++ni)
#pragma unroll
                for (int e = 0; e < 4; ++e) acc[mi][ni][e] = 0.f;

        uint4 pf[4];
#pragma unroll
        for (int i = 0; i < 4; ++i)
            pf[i] = *(const uint4*)(g_Kh + (size_t)(n0 + srow) * D_DIM + scol + i * 8);

#pragma unroll 1
        for (int kc = 0; kc < 8; ++kc) {
            __syncthreads();
#pragma unroll
            for (int i = 0; i < 4; ++i)
                *(uint4*)(Ks + srow * KS_STRIDE + scol + i * 8) = pf[i];
            __syncthreads();
            if (kc < 7) {
                const int knext = (kc + 1) * 64;
#pragma unroll
                for (int i = 0; i < 4; ++i)
                    pf[i] = *(const uint4*)(g_Kh + (size_t)(n0 + srow) * D_DIM + knext + scol + i * 8);
            }
            const int k0 = kc * 64;
#pragma unroll
            for (int kk = 0; kk < 64; kk += 16) {
                unsigned a[2][4], b[4][2];
#pragma unroll
                for (int mi = 0; mi < 2; ++mi) {
                    const __half* ap = Qs + (wm * 32 + mi * 16 + g) * QS_STRIDE + k0 + kk + tig * 2;
                    a[mi][0] = *(const unsigned*)(ap);
                    a[mi][1] = *(const unsigned*)(ap + 8 * QS_STRIDE);
                    a[mi][2] = *(const unsigned*)(ap + 8);
                    a[mi][3] = *(const unsigned*)(ap + 8 * QS_STRIDE + 8);
                }
#pragma unroll
                for (int ni = 0; ni < 4; ++ni) {
                    const __half* bp = Ks + (wn * 32 + ni * 8 + g) * KS_STRIDE + kk + tig * 2;
                    b[ni][0] = *(const unsigned*)(bp);
                    b[ni][1] = *(const unsigned*)(bp + 8);
                }
#pragma unroll
                for (int mi = 0; mi < 2; ++mi)
#pragma unroll
                    for (int ni = 0; ni < 4; ++ni)
                        mma16816(acc[mi][ni], a[mi], b[ni]);
            }
        }
        // sharpening epilogue -> Ws (fp16)
#pragma unroll
        for (int mi = 0; mi < 2; ++mi) {
#pragma unroll
            for (int ni = 0; ni < 4; ++ni) {
                const int rr = wm * 32 + mi * 16 + g;
                const int cc = n0 + wn * 32 + ni * 8 + tig * 2;
                *(__half2*)(Ws + rr * WS_STRIDE + cc) =
                    __floats2half2_rn(sharp_fn(acc[mi][ni][0]), sharp_fn(acc[mi][ni][1]));
                *(__half2*)(Ws + (rr + 8) * WS_STRIDE + cc) =
                    __floats2half2_rn(sharp_fn(acc[mi][ni][2]), sharp_fn(acc[mi][ni][3]));
            }
        }
    }
    __syncthreads();

    // ---- Step 2: row sums of sharpened weights -> inv = 1/rowsum ----
    {
        const int r = tid >> 2;
        const int p = tid & 3;
        const __half* wr = Ws + r * WS_STRIDE + p * 256;
        float s = 0.f;
#pragma unroll 8
        for (int i = 0; i < 256; i += 2) {
            float2 f = __half22float2(*(const __half2*)(wr + i));
            s += f.x + f.y;
        }
        red[tid] = s;
        __syncthreads();
        if (tid < M_TILE)
            inv[tid] = 1.f / (red[tid * 4] + red[tid * 4 + 1] +
                              red[tid * 4 + 2] + red[tid * 4 + 3]);
        __syncthreads();
    }

    // ---- Step 3: GEMM2 (out = (1/rowsum) * Ws @ val) ----
#pragma unroll 1
    for (int nc = 0; nc < 8; ++nc) {
        const int n0 = nc * 128;
        float acc[2][4][4];
#pragma unroll
        for (int mi = 0; mi < 2; ++mi)
#pragma unroll
            for (int ni = 0; ni < 4; ++ni)
#pragma unroll
                for (int e = 0; e < 4; ++e) acc[mi][ni][e] = 0.f;

        uint4 pf[4];
#pragma unroll
        for (int i = 0; i < 4; ++i)
            pf[i] = *(const uint4*)(g_Vt + (size_t)(n0 + srow) * C_DIM + scol + i * 8);

#pragma unroll 1
        for (int kc = 0; kc < 16; ++kc) {
            __syncthreads();
#pragma unroll
            for (int i = 0; i < 4; ++i)
                *(uint4*)(Ks + srow * KS_STRIDE + scol + i * 8) = pf[i];
            __syncthreads();
            if (kc < 15) {
                const int knext = (kc + 1) * 64;
#pragma unroll
                for (int i = 0; i < 4; ++i)
                    pf[i] = *(const uint4*)(g_Vt + (size_t)(n0 + srow) * C_DIM + knext + scol + i * 8);
            }
            const int k0 = kc * 64;
#pragma unroll
            for (int kk = 0; kk < 64; kk += 16) {
                unsigned a[2][4], b[4][2];
#pragma unroll
                for (int mi = 0; mi < 2; ++mi) {
                    const __half* ap = Ws + (wm * 32 + mi * 16 + g) * WS_STRIDE + k0 + kk + tig * 2;
                    a[mi][0] = *(const unsigned*)(ap);
                    a[mi][1] = *(const unsigned*)(ap + 8 * WS_STRIDE);
                    a[mi][2] = *(const unsigned*)(ap + 8);
                    a[mi][3] = *(const unsigned*)(ap + 8 * WS_STRIDE + 8);
                }
#pragma unroll
                for (int ni = 0; ni < 4; ++ni) {
                    const __half* bp = Ks + (wn * 32 + ni * 8 + g) * KS_STRIDE + kk + tig * 2;
                    b[ni][0] = *(const unsigned*)(bp);
                    b[ni][1] = *(const unsigned*)(bp + 8);
                }
#pragma unroll
                for (int mi = 0; mi < 2; ++mi)
#pragma unroll
                    for (int ni = 0; ni < 4; ++ni)
                        mma16816(acc[mi][ni], a[mi], b[ni]);
            }
        }
        // scale + store epilogue
#pragma unroll
        for (int mi = 0; mi < 2; ++mi) {
#pragma unroll
            for (int ni = 0; ni < 4; ++ni) {
                const int rr = wm * 32 + mi * 16 + g;
                const int cc = n0 + wn * 32 + ni * 8 + tig * 2;
                const float i0 = inv[rr];
                const float i8 = inv[rr + 8];
                float2 o;
                o.x = acc[mi][ni][0] * i0;
                o.y = acc[mi][ni][1] * i0;
                *(float2*)(out + (size_t)(row0 + rr) * C_DIM + cc) = o;
                o.x = acc[mi][ni][2] * i8;
                o.y = acc[mi][ni][3] * i8;
                *(float2*)(out + (size_t)(row0 + rr + 8) * C_DIM + cc) = o;
            }
        }
    }
}

// ---------------------------------------------------------------------------
extern "C" void kernel_launch(void* const* d_in, const int* in_sizes, int n_in,
                              void* d_out, int out_size) {
    const float* query = (const float*)d_in[0];
    const float* key   = (const float*)d_in[1];
    const float* val   = (const float*)d_in[2];
    float* out = (float*)d_out;

    const int B = in_sizes[0] / D_DIM;

    normalize_key_kernel<<<C_DIM, 128>>>(key);
    transpose_val_kernel<<<dim3(C_DIM / 32, C_DIM / 32), dim3(32, 8)>>>(val);

    const int smem_bytes = (M_TILE * QS_STRIDE + M_TILE * WS_STRIDE + 128 * KS_STRIDE) * 2
                         + (256 + 64) * 4;
    cudaFuncSetAttribute(fused_kv_kernel,
                         cudaFuncAttributeMaxDynamicSharedMemorySize, smem_bytes);
    fused_kv_kernel<<<B / M_TILE, 256, smem_bytes>>>(query, out);
}

// round 6
// speedup vs baseline: 1.7023x; 1.7023x over previous
#include <cuda_runtime.h>
#include <cuda_fp16.h>
#include <cstdint>

#define D_DIM 512
#define C_DIM 1024
#define M_TILE 64

// smem layout (bytes)
#define QOFF   0            // 64 x 512 fp16, 8 panels of (64 rows x 128B), SW128
#define WOFF   65536        // 64 x 1024 fp16, 16 panels of (64 rows x 128B), SW128
#define SBOFF  196608       // 2 x 16384: B staging, 128 rows x 128B, SW128
#define REDOFF 229376       // 256 floats
#define INVOFF 230400       // 64 floats
#define SMEM_BYTES 230656

// ---- small device scratch (3 MiB total: proven OK in Round 2) ----
__device__ __half g_Kh[C_DIM * D_DIM];   // normalized keys fp16 (row-major, K-major)
__device__ __half g_Vt[C_DIM * C_DIM];   // val transposed fp16: g_Vt[n*C+k] = val[k*C+n]

// ---- helpers ----
__device__ __forceinline__ uint32_t smem_u32(const void* p) {
    uint32_t a;
    asm("{ .reg .u64 t; cvta.to.shared.u64 t, %1; cvt.u32.u64 %0, t; }" : "=r"(a) : "l"(p));
    return a;
}
#define SWZ(x) ((x) ^ (((x) >> 3) & 0x70))

__device__ __forceinline__ void cp16(uint32_t s, const void* g) {
    asm volatile("cp.async.cg.shared.global [%0], [%1], 16;" :: "r"(s), "l"(g));
}
#define CP_COMMIT() asm volatile("cp.async.commit_group;" ::: "memory")
#define CP_WAIT1()  asm volatile("cp.async.wait_group 1;" ::: "memory")
#define CP_WAIT0()  asm volatile("cp.async.wait_group 0;" ::: "memory")

__device__ __forceinline__ void ldsm4(unsigned r[4], uint32_t a) {
    asm volatile("ldmatrix.sync.aligned.m8n8.x4.shared.b16 {%0,%1,%2,%3}, [%4];"
                 : "=r"(r[0]), "=r"(r[1]), "=r"(r[2]), "=r"(r[3]) : "r"(a));
}
__device__ __forceinline__ void mma16816(float c[4], const unsigned a[4], const unsigned b[2]) {
    asm volatile(
        "mma.sync.aligned.m16n8k16.row.col.f32.f16.f16.f32 "
        "{%0,%1,%2,%3}, {%4,%5,%6,%7}, {%8,%9}, {%0,%1,%2,%3};\n"
        : "+f"(c[0]), "+f"(c[1]), "+f"(c[2]), "+f"(c[3])
        : "r"(a[0]), "r"(a[1]), "r"(a[2]), "r"(a[3]), "r"(b[0]), "r"(b[1]));
}

// sharp(x) = sigmoid(10x-5) + sigmoid(-10x-5)
__device__ __forceinline__ float sharp_fn(float x) {
    const float E = 148.4131591f;      // e^5
    const float E2p1 = 22027.4658f;    // e^10 + 1
    float u = __expf(10.f * x);
    float eu = E * u;
    float num = fmaf(eu, u, fmaf(2.f, u, E));
    float den = fmaf(eu, u, fmaf(E2p1, u, E));
    return __fdividef(num, den);
}

// stage one B chunk: 128 rows x 64 cols fp16 from gsrc (row stride ldb halves)
__device__ __forceinline__ void fillB(const __half* __restrict__ gsrc, int ldb,
                                      uint32_t dst, int tid) {
#pragma unroll
    for (int it = 0; it < 4; ++it) {
        int idx = it * 256 + tid;
        int r = idx >> 3, c = idx & 7;
        cp16(dst + SWZ(r * 128 + c * 16), gsrc + (size_t)r * ldb + c * 8);
    }
}

// ---- prep kernels ----
__global__ void normalize_key_kernel(const float* __restrict__ key) {
    const int r = blockIdx.x;
    const int tid = threadIdx.x;  // 128
    const float* kr = key + (size_t)r * D_DIM;
    float v[4];
    float ss = 0.f;
#pragma unroll
    for (int i = 0; i < 4; ++i) { v[i] = kr[tid + i * 128]; ss += v[i] * v[i]; }
    __shared__ float ws[4];
    __shared__ float sinv;
#pragma unroll
    for (int o = 16; o > 0; o >>= 1) ss += __shfl_down_sync(0xffffffffu, ss, o);
    if ((tid & 31) == 0) ws[tid >> 5] = ss;
    __syncthreads();
    if (tid == 0) sinv = rsqrtf(ws[0] + ws[1] + ws[2] + ws[3] + 1e-12f);
    __syncthreads();
    const float iv = sinv;
#pragma unroll
    for (int i = 0; i < 4; ++i)
        g_Kh[(size_t)r * D_DIM + tid + i * 128] = __float2half(v[i] * iv);
}

__global__ void transpose_val_kernel(const float* __restrict__ val) {
    __shared__ float tile[32][33];
    const int ko = blockIdx.x * 32;
    const int no = blockIdx.y * 32;
    const int tx = threadIdx.x, ty = threadIdx.y;  // (32, 8)
#pragma unroll
    for (int j = 0; j < 32; j += 8)
        tile[ty + j][tx] = val[(size_t)(ko + ty + j) * C_DIM + no + tx];
    __syncthreads();
#pragma unroll
    for (int j = 0; j < 32; j += 8)
        g_Vt[(size_t)(no + ty + j) * C_DIM + ko + tx] = __float2half(tile[tx][ty + j]);
}

// ---- fused main kernel ----
__global__ __launch_bounds__(256, 1)
void fused_kv_kernel(const float* __restrict__ query, float* __restrict__ out) {
    extern __shared__ char smem[];
    const uint32_t sb = smem_u32(smem);
    float* red = (float*)(smem + REDOFF);
    float* inv = (float*)(smem + INVOFF);

    const int tid  = threadIdx.x;
    const int lane = tid & 31;
    const int wid  = tid >> 5;
    const int wm   = wid >> 2;          // 0..1 (32 rows each)
    const int wn   = wid & 3;           // 0..3 (32 cols each within 128-chunk)
    const int g    = lane >> 2;         // 0..7
    const int tig  = lane & 3;          // 0..3
    const int lrow = lane & 15;
    const int hs   = lane >> 4;         // 0..1 col-half selector for ldmatrix
    const int row0 = blockIdx.x * M_TILE;

    // ---- Step 0: load + l2-normalize Q tile into swizzled smem ----
    {
        const int r = tid >> 2;           // 0..63
        const int p = tid & 3;            // covers panels 2p, 2p+1
        const float* qrow = query + (size_t)(row0 + r) * D_DIM + p * 128;
        float ss = 0.f;
#pragma unroll
        for (int q = 0; q < 2; ++q) {
            uint32_t pb = sb + QOFF + (2 * p + q) * 8192;
#pragma unroll 4
            for (int j = 0; j < 64; j += 4) {
                float4 v = *(const float4*)(qrow + q * 64 + j);
                ss += v.x * v.x + v.y * v.y + v.z * v.z + v.w * v.w;
                int b = r * 128 + j * 2;
                *(__half2*)(smem + (pb - sb) + SWZ(b))     = __floats2half2_rn(v.x, v.y);
                *(__half2*)(smem + (pb - sb) + SWZ(b + 4)) = __floats2half2_rn(v.z, v.w);
            }
        }
        red[tid] = ss;
        __syncthreads();
        if (tid < M_TILE)
            inv[tid] = rsqrtf(red[tid * 4] + red[tid * 4 + 1] +
                              red[tid * 4 + 2] + red[tid * 4 + 3] + 1e-12f);
        __syncthreads();
        const float qin = inv[r];
#pragma unroll
        for (int q = 0; q < 2; ++q) {
            char* pb = smem + QOFF + (2 * p + q) * 8192;
#pragma unroll 8
            for (int b = 0; b < 128; b += 4) {
                __half2* hp = (__half2*)(pb + SWZ(r * 128 + b));
                float2 f = __half22float2(*hp);
                *hp = __floats2half2_rn(f.x * qin, f.y * qin);
            }
        }
    }
    __syncthreads();

    float acc[2][4][4];

    // ---- GEMM1: W = sharp(Qn @ Kn^T), 64 pipelined iterations (8 nc x 8 kc) ----
    fillB(g_Kh, D_DIM, sb + SBOFF, tid);
    CP_COMMIT();
    fillB(g_Kh + 64, D_DIM, sb + SBOFF + 16384, tid);
    CP_COMMIT();
    CP_WAIT1();
    __syncthreads();

#pragma unroll 1
    for (int t = 0; t < 64; ++t) {
        const int nc = t >> 3, kc = t & 7;
        if (kc == 0) {
#pragma unroll
            for (int mi = 0; mi < 2; ++mi)
#pragma unroll
                for (int ni = 0; ni < 4; ++ni)
#pragma unroll
                    for (int e = 0; e < 4; ++e) acc[mi][ni][e] = 0.f;
        }
        const uint32_t sB = sb + SBOFF + (t & 1) * 16384;
        const uint32_t sA = sb + QOFF + kc * 8192;
#pragma unroll
        for (int ks = 0; ks < 4; ++ks) {
            unsigned a[2][4], b[4][2];
#pragma unroll
            for (int mi = 0; mi < 2; ++mi) {
                int ar = wm * 32 + mi * 16 + lrow;
                ldsm4(a[mi], sA + SWZ(ar * 128 + ks * 32 + hs * 16));
            }
#pragma unroll
            for (int pr = 0; pr < 2; ++pr) {
                unsigned r4[4];
                int nr = wn * 32 + pr * 16 + lrow;
                ldsm4(r4, sB + SWZ(nr * 128 + ks * 32 + hs * 16));
                b[pr * 2][0] = r4[0]; b[pr * 2 + 1][0] = r4[1];
                b[pr * 2][1] = r4[2]; b[pr * 2 + 1][1] = r4[3];
            }
#pragma unroll
            for (int mi = 0; mi < 2; ++mi)
#pragma unroll
                for (int ni = 0; ni < 4; ++ni)
                    mma16816(acc[mi][ni], a[mi], b[ni]);
        }
        if (kc == 7) {
            // sharpen -> W smem
#pragma unroll
            for (int mi = 0; mi < 2; ++mi) {
#pragma unroll
                for (int ni = 0; ni < 4; ++ni) {
                    int rr = wm * 32 + mi * 16 + g;
                    int cc = nc * 128 + wn * 32 + ni * 8 + tig * 2;
                    int panel = cc >> 6, c6 = cc & 63;
                    char* base = smem + WOFF + panel * 8192;
                    *(__half2*)(base + SWZ(rr * 128 + c6 * 2)) =
                        __floats2half2_rn(sharp_fn(acc[mi][ni][0]), sharp_fn(acc[mi][ni][1]));
                    *(__half2*)(base + SWZ((rr + 8) * 128 + c6 * 2)) =
                        __floats2half2_rn(sharp_fn(acc[mi][ni][2]), sharp_fn(acc[mi][ni][3]));
                }
            }
        }
        __syncthreads();
        if (t + 2 < 64) {
            int u = t + 2;
            fillB(g_Kh + (size_t)((u >> 3) * 128) * D_DIM + (u & 7) * 64, D_DIM,
                  sb + SBOFF + (u & 1) * 16384, tid);
        }
        CP_COMMIT();
        CP_WAIT1();
        __syncthreads();
    }
    CP_WAIT0();
    __syncthreads();

    // ---- rowsum of W -> inv ----
    {
        const int r = tid >> 2, p = tid & 3;
        float s = 0.f;
#pragma unroll
        for (int q = 0; q < 4; ++q) {
            const uint4* rp = (const uint4*)(smem + WOFF + (p * 4 + q) * 8192 + r * 128);
#pragma unroll
            for (int i = 0; i < 8; ++i) {
                uint4 v = rp[i];
                const __half2* h2 = (const __half2*)&v;
#pragma unroll
                for (int j = 0; j < 4; ++j) {
                    float2 f = __half22float2(h2[j]);
                    s += f.x + f.y;
                }
            }
        }
        red[tid] = s;
        __syncthreads();
        if (tid < M_TILE)
            inv[tid] = 1.f / (red[tid * 4] + red[tid * 4 + 1] +
                              red[tid * 4 + 2] + red[tid * 4 + 3]);
        __syncthreads();
    }

    // ---- GEMM2: out = (1/rowsum) * W @ val, 128 iterations (8 nc x 16 kc) ----
    fillB(g_Vt, C_DIM, sb + SBOFF, tid);
    CP_COMMIT();
    fillB(g_Vt + 64, C_DIM, sb + SBOFF + 16384, tid);
    CP_COMMIT();
    CP_WAIT1();
    __syncthreads();

#pragma unroll 1
    for (int t = 0; t < 128; ++t) {
        const int nc = t >> 4, kc = t & 15;
        if (kc == 0) {
#pragma unroll
            for (int mi = 0; mi < 2; ++mi)
#pragma unroll
                for (int ni = 0; ni < 4; ++ni)
#pragma unroll
                    for (int e = 0; e < 4; ++e) acc[mi][ni][e] = 0.f;
        }
        const uint32_t sB = sb + SBOFF + (t & 1) * 16384;
        const uint32_t sA = sb + WOFF + kc * 8192;
#pragma unroll
        for (int ks = 0; ks < 4; ++ks) {
            unsigned a[2][4], b[4][2];
#pragma unroll
            for (int mi = 0; mi < 2; ++mi) {
                int ar = wm * 32 + mi * 16 + lrow;
                ldsm4(a[mi], sA + SWZ(ar * 128 + ks * 32 + hs * 16));
            }
#pragma unroll
            for (int pr = 0; pr < 2; ++pr) {
                unsigned r4[4];
                int nr = wn * 32 + pr * 16 + lrow;
                ldsm4(r4, sB + SWZ(nr * 128 + ks * 32 + hs * 16));
                b[pr * 2][0] = r4[0]; b[pr * 2 + 1][0] = r4[1];
                b[pr * 2][1] = r4[2]; b[pr * 2 + 1][1] = r4[3];
            }
#pragma unroll
            for (int mi = 0; mi < 2; ++mi)
#pragma unroll
                for (int ni = 0; ni < 4; ++ni)
                    mma16816(acc[mi][ni], a[mi], b[ni]);
        }
        if (kc == 15) {
#pragma unroll
            for (int mi = 0; mi < 2; ++mi) {
#pragma unroll
                for (int ni = 0; ni < 4; ++ni) {
                    int rr = wm * 32 + mi * 16 + g;
                    int cc = nc * 128 + wn * 32 + ni * 8 + tig * 2;
                    float i0 = inv[rr], i8 = inv[rr + 8];
                    *(float2*)(out + (size_t)(row0 + rr) * C_DIM + cc) =
                        make_float2(acc[mi][ni][0] * i0, acc[mi][ni][1] * i0);
                    *(float2*)(out + (size_t)(row0 + rr + 8) * C_DIM + cc) =
                        make_float2(acc[mi][ni][2] * i8, acc[mi][ni][3] * i8);
                }
            }
        }
        __syncthreads();
        if (t + 2 < 128) {
            int u = t + 2;
            fillB(g_Vt + (size_t)((u >> 4) * 128) * C_DIM + (u & 15) * 64, C_DIM,
                  sb + SBOFF + (u & 1) * 16384, tid);
        }
        CP_COMMIT();
        CP_WAIT1();
        __syncthreads();
    }
}

// ---------------------------------------------------------------------------
extern "C" void kernel_launch(void* const* d_in, const int* in_sizes, int n_in,
                              void* d_out, int out_size) {
    const float* query = (const float*)d_in[0];
    const float* key   = (const float*)d_in[1];
    const float* val   = (const float*)d_in[2];
    float* out = (float*)d_out;

    const int B = in_sizes[0] / D_DIM;

    normalize_key_kernel<<<C_DIM, 128>>>(key);
    transpose_val_kernel<<<dim3(C_DIM / 32, C_DIM / 32), dim3(32, 8)>>>(val);

    cudaFuncSetAttribute(fused_kv_kernel,
                         cudaFuncAttributeMaxDynamicSharedMemorySize, SMEM_BYTES);
    fused_kv_kernel<<<B / M_TILE, 256, SMEM_BYTES>>>(query, out);
}